// round 12
// baseline (speedup 1.0000x reference)
#include <cuda_runtime.h>
#include <cuda_bf16.h>

#define N_NODES 50000
#define N_EDGES 800000
#define D 64

// ---- device-global scratch (no allocations allowed) ----
__device__ __align__(16) float g_denom[N_NODES];
__device__ __align__(16) float g_hunnorm[N_NODES * D];   // un-normalized msg sums

// ---------------------------------------------------------------------------
// Fused edge kernel, 4 edges per half-warp (ILP=4):
//   8 independent 16B loads in flight, 4 interleaved shfl-reduce chains,
//   ex = exp(dot);  hunnorm[dst] += ex*hv (red.v4);  denom[dst] += ex.
// src/dst indices fetched as one int4 each (eb is 4-aligned).
// ---------------------------------------------------------------------------
__global__ void __launch_bounds__(256) kgcn_edge_kernel(
        const float* __restrict__ h_src,
        const float* __restrict__ e,
        const int* __restrict__ src,
        const int* __restrict__ dst) {
    int tid = blockIdx.x * blockDim.x + threadIdx.x;
    int grp = tid >> 4;          // half-warp group id (200000 groups exactly)
    int sub = tid & 15;
    int eb  = grp * 4;

    int4 s4 = *reinterpret_cast<const int4*>(&src[eb]);
    int4 d4 = *reinterpret_cast<const int4*>(&dst[eb]);

    const float4* h4 = reinterpret_cast<const float4*>(h_src);
    const float4* e4 = reinterpret_cast<const float4*>(e);

    float4 ev0 = e4[(size_t)(eb + 0) * 16 + sub];
    float4 ev1 = e4[(size_t)(eb + 1) * 16 + sub];
    float4 ev2 = e4[(size_t)(eb + 2) * 16 + sub];
    float4 ev3 = e4[(size_t)(eb + 3) * 16 + sub];
    float4 hv0 = h4[(size_t)s4.x * 16 + sub];
    float4 hv1 = h4[(size_t)s4.y * 16 + sub];
    float4 hv2 = h4[(size_t)s4.z * 16 + sub];
    float4 hv3 = h4[(size_t)s4.w * 16 + sub];

    float t0 = hv0.x * ev0.x + hv0.y * ev0.y + hv0.z * ev0.z + hv0.w * ev0.w;
    float t1 = hv1.x * ev1.x + hv1.y * ev1.y + hv1.z * ev1.z + hv1.w * ev1.w;
    float t2 = hv2.x * ev2.x + hv2.y * ev2.y + hv2.z * ev2.z + hv2.w * ev2.w;
    float t3 = hv3.x * ev3.x + hv3.y * ev3.y + hv3.z * ev3.z + hv3.w * ev3.w;

    #pragma unroll
    for (int o = 1; o < 16; o <<= 1) {
        t0 += __shfl_xor_sync(0xffffffffu, t0, o);
        t1 += __shfl_xor_sync(0xffffffffu, t1, o);
        t2 += __shfl_xor_sync(0xffffffffu, t2, o);
        t3 += __shfl_xor_sync(0xffffffffu, t3, o);
    }

    float ex0 = __expf(t0);
    float ex1 = __expf(t1);
    float ex2 = __expf(t2);
    float ex3 = __expf(t3);

    float* a0 = &g_hunnorm[(size_t)d4.x * D + sub * 4];
    float* a1 = &g_hunnorm[(size_t)d4.y * D + sub * 4];
    float* a2 = &g_hunnorm[(size_t)d4.z * D + sub * 4];
    float* a3 = &g_hunnorm[(size_t)d4.w * D + sub * 4];
    asm volatile("red.global.add.v4.f32 [%0], {%1, %2, %3, %4};"
                 :: "l"(a0), "f"(ex0 * hv0.x), "f"(ex0 * hv0.y),
                    "f"(ex0 * hv0.z), "f"(ex0 * hv0.w) : "memory");
    asm volatile("red.global.add.v4.f32 [%0], {%1, %2, %3, %4};"
                 :: "l"(a1), "f"(ex1 * hv1.x), "f"(ex1 * hv1.y),
                    "f"(ex1 * hv1.z), "f"(ex1 * hv1.w) : "memory");
    asm volatile("red.global.add.v4.f32 [%0], {%1, %2, %3, %4};"
                 :: "l"(a2), "f"(ex2 * hv2.x), "f"(ex2 * hv2.y),
                    "f"(ex2 * hv2.z), "f"(ex2 * hv2.w) : "memory");
    asm volatile("red.global.add.v4.f32 [%0], {%1, %2, %3, %4};"
                 :: "l"(a3), "f"(ex3 * hv3.x), "f"(ex3 * hv3.y),
                    "f"(ex3 * hv3.z), "f"(ex3 * hv3.w) : "memory");
    if (sub == 0) {
        atomicAdd(&g_denom[d4.x], ex0);
        atomicAdd(&g_denom[d4.y], ex1);
        atomicAdd(&g_denom[d4.z], ex2);
        atomicAdd(&g_denom[d4.w], ex3);
    }
}

// ---------------------------------------------------------------------------
// Output GEMM v4: out = concat(h_dst, hunnorm/denom) @ W^T + b
// Block: 128 threads -> 128-node x 64-col tile; thread: 8 nodes x 8 cols.
// Inner loop per kk: 4x LDS128 (2 W-slices + 2 broadcast h-slices) + 64 FMA
// -> LDS:FMA = 1:16 issues; 64-deep independent FMA chains.
// smem: W_s 32KB + h_s 16.5KB = 48.5KB; 391 blocks, single resident wave.
// ---------------------------------------------------------------------------
#define HT_STRIDE 132   // 128 + 4 pad, multiple of 4 for float4 alignment
__global__ void __launch_bounds__(128) kgcn_out_kernel(
        const float* __restrict__ h_dst,
        const float* __restrict__ W,
        const float* __restrict__ b,
        float* __restrict__ out) {
    __shared__ float W_s[128 * 64];          // [k][j] transposed, 32KB
    __shared__ float h_s[32 * HT_STRIDE];    // [kk][node], padded

    const int tid = threadIdx.x;
    for (int i = tid; i < 64 * 128; i += 128) {
        int j = i >> 7;     // out col
        int k = i & 127;    // in  idx
        W_s[k * 64 + j] = W[i];
    }

    const int tx = tid & 7;       // cols  8*tx .. 8*tx+7
    const int ty = tid >> 3;      // nodes 8*ty .. 8*ty+7   (0..15)
    const int node0 = blockIdx.x * 128;

    float acc[8][8];
    #pragma unroll
    for (int n = 0; n < 8; n++)
        #pragma unroll
        for (int j = 0; j < 8; j++) acc[n][j] = 0.f;

    #pragma unroll
    for (int c = 0; c < 4; c++) {
        const float* srcp = (c < 2) ? h_dst : g_hunnorm;
        const int kof4 = (c & 1) * 8;

        __syncthreads();   // c==0: covers W_s; c>0: prev chunk readers done
        // Stage 128 nodes x 32 k, transposed: 1024 float4 loads, 8/thread.
        #pragma unroll
        for (int r = 0; r < 8; r++) {
            int idx = tid + r * 128;    // 0..1023
            int n   = idx >> 3;         // local node 0..127
            int q   = idx & 7;          // float4 k-slot 0..7
            int gn  = node0 + n;
            float4 v = make_float4(0.f, 0.f, 0.f, 0.f);
            if (gn < N_NODES) {
                v = reinterpret_cast<const float4*>(srcp)[(size_t)gn * 16 + kof4 + q];
                if (c >= 2) {
                    float dn = g_denom[gn];
                    float inv = (dn != 0.f) ? (1.0f / dn) : 0.f;  // edge-less -> 0
                    v.x *= inv; v.y *= inv; v.z *= inv; v.w *= inv;
                }
            }
            h_s[(q * 4 + 0) * HT_STRIDE + n] = v.x;
            h_s[(q * 4 + 1) * HT_STRIDE + n] = v.y;
            h_s[(q * 4 + 2) * HT_STRIDE + n] = v.z;
            h_s[(q * 4 + 3) * HT_STRIDE + n] = v.w;
        }
        __syncthreads();

        const float* Wrow = &W_s[(c * 32) * 64 + 8 * tx];
        #pragma unroll 4
        for (int kk = 0; kk < 32; kk++) {
            float4 wa = *reinterpret_cast<const float4*>(Wrow + kk * 64);
            float4 wb = *reinterpret_cast<const float4*>(Wrow + kk * 64 + 4);
            float4 ha = *reinterpret_cast<const float4*>(&h_s[kk * HT_STRIDE + 8 * ty]);
            float4 hb = *reinterpret_cast<const float4*>(&h_s[kk * HT_STRIDE + 8 * ty + 4]);
            float wv[8] = {wa.x, wa.y, wa.z, wa.w, wb.x, wb.y, wb.z, wb.w};
            float hn[8] = {ha.x, ha.y, ha.z, ha.w, hb.x, hb.y, hb.z, hb.w};
            #pragma unroll
            for (int n = 0; n < 8; n++)
                #pragma unroll
                for (int j = 0; j < 8; j++)
                    acc[n][j] = fmaf(hn[n], wv[j], acc[n][j]);
        }
    }

    float4 b0 = *reinterpret_cast<const float4*>(&b[8 * tx]);
    float4 b1 = *reinterpret_cast<const float4*>(&b[8 * tx + 4]);
    #pragma unroll
    for (int n = 0; n < 8; n++) {
        int gn = node0 + 8 * ty + n;
        if (gn < N_NODES) {
            float4 o0 = make_float4(acc[n][0] + b0.x, acc[n][1] + b0.y,
                                    acc[n][2] + b0.z, acc[n][3] + b0.w);
            float4 o1 = make_float4(acc[n][4] + b1.x, acc[n][5] + b1.y,
                                    acc[n][6] + b1.z, acc[n][7] + b1.w);
            reinterpret_cast<float4*>(out)[(size_t)gn * 16 + 2 * tx + 0] = o0;
            reinterpret_cast<float4*>(out)[(size_t)gn * 16 + 2 * tx + 1] = o1;
        }
    }
}

// ---------------------------------------------------------------------------
// Launch.  Inputs: 0 h_src, 1 h_dst, 2 e, 3 src, 4 dst, 5 W, 6 b
// ---------------------------------------------------------------------------
extern "C" void kernel_launch(void* const* d_in, const int* in_sizes, int n_in,
                              void* d_out, int out_size) {
    const float* h_src = (const float*)d_in[0];
    const float* h_dst = (const float*)d_in[1];
    const float* e     = (const float*)d_in[2];
    const int*   src   = (const int*)d_in[3];
    const int*   dst   = (const int*)d_in[4];
    const float* W     = (const float*)d_in[5];
    const float* b     = (const float*)d_in[6];
    float* out = (float*)d_out;

    void* p_hunnorm = nullptr;
    void* p_denom   = nullptr;
    cudaGetSymbolAddress(&p_hunnorm, g_hunnorm);
    cudaGetSymbolAddress(&p_denom,   g_denom);
    cudaMemsetAsync(p_hunnorm, 0, sizeof(float) * N_NODES * D);
    cudaMemsetAsync(p_denom,   0, sizeof(float) * N_NODES);

    // 200000 half-warp groups * 4 edges; 16 groups per 256-thread block
    kgcn_edge_kernel<<<12500, 256>>>(h_src, e, src, dst);
    // 391 blocks of 128 nodes, 128 threads each — single resident wave
    kgcn_out_kernel<<<(N_NODES + 127) / 128, 128>>>(h_dst, W, b, out);
}